// round 1
// baseline (speedup 1.0000x reference)
#include <cuda_runtime.h>

// SubsampledRelativeAttention closed form:
//   h = b % 8, c = t >> 2
//   out[b,t,s] = dot(q[b,t,:], e1[h, 255 + s - c, :])  if s <= c
//              = dot(q[b,t,:], e2[h, s - c, :])        if s >  c
// Equivalently a banded GEMM against E = [e1 ; e2[1:]] (511 rows), with
// out[b,t,s] = q[b,t] . E[h, j],  j = 255 - c + s  (j in [255-c, 510-c]).
//
// Kernel: one block per (b, 128-row t-tile). K=64 fits entirely in smem.
// For each tile, c spans 32 values -> union band width 287, covered by 5
// chunks of 64 E-rows. Each (t,s) lands in exactly one chunk, so chunk
// results are written directly (no cross-chunk accumulation).

#define BB 128
#define TT 1024
#define SS 256
#define DD 64
#define HH 8

constexpr int TM  = 128;      // t rows per block
constexpr int JC  = 64;       // E-rows per chunk
constexpr int NCH = 5;        // chunks (5*64 = 320 >= 287 band width)
constexpr int QLD = TM + 4;   // 132: padded stride, 16B-aligned rows
constexpr int ELD = JC + 4;   // 68:  padded stride, 16B-aligned rows

__global__ __launch_bounds__(256, 2)
void srel_kernel(const float* __restrict__ q,
                 const float* __restrict__ e1,
                 const float* __restrict__ e2,
                 float* __restrict__ out)
{
    __shared__ __align__(16) float Qs[DD][QLD];   // [k][t]  (transposed)
    __shared__ __align__(16) float Es[DD][ELD];   // [k][j]  (transposed)

    const int blk = blockIdx.x;
    const int b   = blk >> 3;             // 8 t-tiles per batch row
    const int t0  = (blk & 7) * TM;
    const int h   = b & (HH - 1);
    const int c0  = t0 >> 2;
    const int jbase = 224 - c0;           // min j over the tile (>= 0)

    const int tid = threadIdx.x;

    // ---- load Q tile (128 x 64) transposed into smem, coalesced LDG ----
    const float* qb = q + ((size_t)b * TT + t0) * DD;
    for (int i = tid; i < TM * DD; i += 256) {
        const int tt = i >> 6;
        const int k  = i & 63;
        Qs[k][tt] = qb[i];
    }

    // thread tiling: 16 x 16 threads, each computes 8(t) x 4(j)
    const int ty  = tid >> 4;        // 0..15 -> t rows [ty*8, ty*8+8)
    const int tx  = tid & 15;        // 0..15 -> j cols [tx*4, tx*4+4)
    const int tb  = ty * 8;
    const int jj0 = tx * 4;

    const float* e1h = e1 + (size_t)h * SS * DD;
    const float* e2h = e2 + (size_t)h * SS * DD;

    for (int ch = 0; ch < NCH; ch++) {
        const int jc = jbase + ch * JC;

        __syncthreads();   // protects Qs (first iter) and Es reuse (later iters)

        // ---- load E chunk (64 x 64) transposed into smem ----
        for (int i = tid; i < JC * DD; i += 256) {
            const int jj = i >> 6;
            const int k  = i & 63;
            const int j  = jc + jj;
            const float* src;
            if (j <= 255) {
                src = e1h + (size_t)j * DD;           // E rows [0,255]   = e1
            } else {
                int j2 = j - 255;                     // E rows [256,510] = e2[1:]
                if (j2 > 255) j2 = 255;               // clamp: rows beyond band, never written
                src = e2h + (size_t)j2 * DD;
            }
            Es[k][jj] = src[k];
        }
        __syncthreads();

        // ---- 8x4 register-tiled outer product over full K=64 ----
        float acc[8][4];
        #pragma unroll
        for (int it = 0; it < 8; it++)
            #pragma unroll
            for (int jt = 0; jt < 4; jt++)
                acc[it][jt] = 0.0f;

        #pragma unroll
        for (int k = 0; k < DD; k++) {
            const float4 a0 = *reinterpret_cast<const float4*>(&Qs[k][tb]);
            const float4 a1 = *reinterpret_cast<const float4*>(&Qs[k][tb + 4]);
            const float4 bv = *reinterpret_cast<const float4*>(&Es[k][jj0]);
            const float av[8] = {a0.x, a0.y, a0.z, a0.w, a1.x, a1.y, a1.z, a1.w};
            const float bw[4] = {bv.x, bv.y, bv.z, bv.w};
            #pragma unroll
            for (int it = 0; it < 8; it++)
                #pragma unroll
                for (int jt = 0; jt < 4; jt++)
                    acc[it][jt] = fmaf(av[it], bw[jt], acc[it][jt]);
        }

        // ---- banded epilogue: s = j - 255 + c, write if in [0,256) ----
        #pragma unroll
        for (int it = 0; it < 8; it++) {
            const int t  = t0 + tb + it;
            const int c  = t >> 2;
            const int sb = jj0 + jc - 255 + c;
            float* orow = out + ((size_t)b * TT + t) * SS;
            #pragma unroll
            for (int jt = 0; jt < 4; jt++) {
                const int s = sb + jt;
                if ((unsigned)s < (unsigned)SS) orow[s] = acc[it][jt];
            }
        }
    }
}

extern "C" void kernel_launch(void* const* d_in, const int* in_sizes, int n_in,
                              void* d_out, int out_size)
{
    const float* q  = (const float*)d_in[0];
    const float* e1 = (const float*)d_in[1];
    const float* e2 = (const float*)d_in[2];
    float* out      = (float*)d_out;

    srel_kernel<<<BB * (TT / TM), 256>>>(q, e1, e2, out);
}

// round 2
// speedup vs baseline: 1.7081x; 1.7081x over previous
#include <cuda_runtime.h>
#include <cstdint>

// SubsampledRelativeAttention closed form (validated in R1):
//   h = b % 8, c = t >> 2,  E = [e1 ; e2[1:]] (511 rows)
//   out[b,t,s] = q[b,t] . E[h, j],  j = 255 - c + s
// Banded GEMM computed on the tensor pipe with mma.sync m16n8k8 TF32.
//
// Block: one (b, 64-row t-tile). 4 warps, each 32t x 32j.
// c spans 16 values per tile -> band width 271 -> 5 chunks of 64 E-rows.
// Every (t,s) lands in exactly one chunk -> direct banded stores.

#define TT 1024
#define SS 256
#define DD 64

constexpr int TM  = 64;       // t rows per block
constexpr int JC  = 64;       // E-rows per chunk
constexpr int NCH = 5;        // 5*64 = 320 >= 271 band width
constexpr int STR = DD + 4;   // 68: padded row stride (conflict-free frag loads)

__device__ __forceinline__ uint32_t f2tf32(float x) {
    uint32_t r;
    asm("cvt.rna.tf32.f32 %0, %1;" : "=r"(r) : "f"(x));
    return r;
}

__global__ __launch_bounds__(128, 6)
void srel_tf32_kernel(const float* __restrict__ q,
                      const float* __restrict__ e1,
                      const float* __restrict__ e2,
                      float* __restrict__ out)
{
    __shared__ uint32_t Qs[TM * STR];   // [t][k] tf32
    __shared__ uint32_t Es[JC * STR];   // [j][k] tf32

    const int blk  = blockIdx.x;
    const int b    = blk >> 4;            // 16 t-tiles per batch row
    const int t0   = (blk & 15) * TM;
    const int h    = b & 7;
    const int c0   = t0 >> 2;
    const int jbase = 240 - c0;           // min j over tile (c_max = c0+15), >= 0

    const int tid  = threadIdx.x;
    const int wid  = tid >> 5;
    const int lane = tid & 31;
    const int wt   = wid >> 1;            // warp t-half: rows [wt*32, wt*32+32)
    const int wj   = wid & 1;             // warp j-half: cols [wj*32, wj*32+32)
    const int r    = lane >> 2;           // 0..7
    const int cidx = lane & 3;            // 0..3

    // ---- Q tile (64 x 64) -> smem as tf32, coalesced ----
    const float* qb = q + ((size_t)b * TT + t0) * DD;
    for (int i = tid; i < TM * DD; i += 128) {
        const int tt = i >> 6, k = i & 63;
        Qs[tt * STR + k] = f2tf32(qb[i]);
    }

    const float* e1h = e1 + (size_t)h * SS * DD;
    const float* e2h = e2 + (size_t)h * SS * DD;

    const uint32_t* Aq = Qs + (wt * 32 + r) * STR + cidx;
    const uint32_t* Be = Es + (wj * 32 + r) * STR + cidx;

    for (int ch = 0; ch < NCH; ch++) {
        const int jc = jbase + ch * JC;

        __syncthreads();   // prior mma done with Es; Qs ready (first iter)

        // ---- E chunk (64 x 64) -> smem as tf32 ----
        for (int i = tid; i < JC * DD; i += 128) {
            const int jj = i >> 6, k = i & 63;
            const int j  = jc + jj;
            const float* src;
            if (j <= 255) {
                src = e1h + (size_t)j * DD;          // E rows [0,255] = e1
            } else {
                int j2 = j - 255;                    // E rows [256,510] = e2[1:]
                if (j2 > 255) j2 = 255;              // overrun rows never stored
                src = e2h + (size_t)j2 * DD;
            }
            Es[jj * STR + k] = f2tf32(src[k]);
        }
        __syncthreads();

        // ---- warp 32x32 tile: 2 m-frags x 4 n-frags, K=64 in 8 steps ----
        float acc[2][4][4];
        #pragma unroll
        for (int mt = 0; mt < 2; mt++)
            #pragma unroll
            for (int nt = 0; nt < 4; nt++)
                #pragma unroll
                for (int v = 0; v < 4; v++)
                    acc[mt][nt][v] = 0.0f;

        #pragma unroll
        for (int ks = 0; ks < 8; ks++) {
            const int k0 = ks * 8;
            uint32_t a[2][4], bf[4][2];
            #pragma unroll
            for (int mt = 0; mt < 2; mt++) {
                const uint32_t* p = Aq + mt * 16 * STR + k0;
                a[mt][0] = p[0];
                a[mt][1] = p[8 * STR];
                a[mt][2] = p[4];
                a[mt][3] = p[8 * STR + 4];
            }
            #pragma unroll
            for (int nt = 0; nt < 4; nt++) {
                const uint32_t* p = Be + nt * 8 * STR + k0;
                bf[nt][0] = p[0];
                bf[nt][1] = p[4];
            }
            #pragma unroll
            for (int mt = 0; mt < 2; mt++)
                #pragma unroll
                for (int nt = 0; nt < 4; nt++)
                    asm volatile(
                        "mma.sync.aligned.m16n8k8.row.col.f32.tf32.tf32.f32 "
                        "{%0,%1,%2,%3}, {%4,%5,%6,%7}, {%8,%9}, {%0,%1,%2,%3};"
                        : "+f"(acc[mt][nt][0]), "+f"(acc[mt][nt][1]),
                          "+f"(acc[mt][nt][2]), "+f"(acc[mt][nt][3])
                        : "r"(a[mt][0]), "r"(a[mt][1]), "r"(a[mt][2]), "r"(a[mt][3]),
                          "r"(bf[nt][0]), "r"(bf[nt][1]));
        }

        // ---- banded epilogue: s = j - 255 + c ----
        #pragma unroll
        for (int mt = 0; mt < 2; mt++) {
            #pragma unroll
            for (int half = 0; half < 2; half++) {
                const int t = t0 + wt * 32 + mt * 16 + half * 8 + r;
                const int c = t >> 2;
                float* orow = out + ((size_t)b * TT + t) * SS;
                const int sb = jc + wj * 32 + 2 * cidx - 255 + c;
                #pragma unroll
                for (int nt = 0; nt < 4; nt++) {
                    const int s = sb + nt * 8;
                    const float v0 = acc[mt][nt][half * 2 + 0];
                    const float v1 = acc[mt][nt][half * 2 + 1];
                    if ((unsigned)s < (unsigned)SS)       orow[s]     = v0;
                    if ((unsigned)(s + 1) < (unsigned)SS) orow[s + 1] = v1;
                }
            }
        }
    }
}

extern "C" void kernel_launch(void* const* d_in, const int* in_sizes, int n_in,
                              void* d_out, int out_size)
{
    const float* q  = (const float*)d_in[0];
    const float* e1 = (const float*)d_in[1];
    const float* e2 = (const float*)d_in[2];
    float* out      = (float*)d_out;

    srel_tf32_kernel<<<128 * (TT / TM), 128>>>(q, e1, e2, out);
}